// round 11
// baseline (speedup 1.0000x reference)
#include <cuda_runtime.h>
#include <cstdint>
#include <math.h>

// Problem dims
#define T_STEPS 256
#define BATCH   64
#define DIM     512
#define HID     1024
#define G4      (4*HID)
#define KW      (DIM+HID)

// ---------------- device scratch ----------------
__device__ float g_gx[(size_t)T_STEPS * BATCH * G4];
__device__ float g_h[2 * BATCH * HID];
__device__ unsigned g_bar_count = 0;
__device__ volatile unsigned g_bar_sense = 0;
__device__ int g_flags[128 * 32];   // one 128B line per block, zero-init

// ---------------- atomic sense barrier (replay-safe, used once at end) ----------------
__device__ __forceinline__ void grid_bar_atomic(unsigned nblocks) {
    __threadfence();
    __syncthreads();
    if (threadIdx.x == 0) {
        unsigned s = g_bar_sense;
        unsigned old = atomicAdd(&g_bar_count, 1u);
        if (old == nblocks - 1u) {
            g_bar_count = 0u;
            __threadfence();
            atomicAdd((unsigned*)&g_bar_sense, 1u);
        } else {
            while (g_bar_sense == s) { __nanosleep(32); }
        }
    }
    __syncthreads();
}

// ---------------- mma.sync tf32 helpers ----------------
__device__ __forceinline__ uint32_t smem_u32(const void* p) {
    uint32_t a;
    asm("{ .reg .u64 t; cvta.to.shared.u64 t, %1; cvt.u32.u64 %0, t; }" : "=r"(a) : "l"(p));
    return a;
}
__device__ __forceinline__ uint32_t f2tf32(float f) {
    uint32_t r;
    asm("cvt.rna.tf32.f32 %0, %1;" : "=r"(r) : "f"(f));
    return r;
}
__device__ __forceinline__ void mma_tf32(float* d,
                                         uint32_t a0, uint32_t a1, uint32_t a2, uint32_t a3,
                                         uint32_t b0, uint32_t b1) {
    asm volatile(
        "mma.sync.aligned.m16n8k8.row.col.f32.tf32.tf32.f32 "
        "{%0,%1,%2,%3}, {%4,%5,%6,%7}, {%8,%9}, {%0,%1,%2,%3};"
        : "+f"(d[0]), "+f"(d[1]), "+f"(d[2]), "+f"(d[3])
        : "r"(a0), "r"(a1), "r"(a2), "r"(a3), "r"(b0), "r"(b1));
}
__device__ __forceinline__ void cp16(uint32_t dst, const void* src) {
    asm volatile("cp.async.cg.shared.global [%0], [%1], 16;" :: "r"(dst), "l"(src));
}
__device__ __forceinline__ void cp16ca(uint32_t dst, const void* src) {
    asm volatile("cp.async.ca.shared.global [%0], [%1], 16;" :: "r"(dst), "l"(src));
}
#define CP_COMMIT() asm volatile("cp.async.commit_group;" ::: "memory")
#define CP_WAIT(n)  asm volatile("cp.async.wait_group %0;" :: "n"(n) : "memory")

// =====================================================================
// Phase A: gx = X @ Wx^T + b  via mma.sync tf32.
// BM=128, BN=128, BK=32, 256 threads (8 warps: 4 m-warps x 2 n-warps),
// warp tile m32 x n64, cp.async double-buffered, 2 CTAs/SM.
// =====================================================================
#define GA_BK 32
#define GA_STR 36
#define GA_ABUF (128 * GA_STR)
#define GA_SMEM (4 * GA_ABUF * 4)

__global__ __launch_bounds__(256, 2) void gemm_x_tc(
    const float* __restrict__ X,
    const float* __restrict__ Wf, const float* __restrict__ bfv,
    const float* __restrict__ Wi, const float* __restrict__ biv,
    const float* __restrict__ Wg, const float* __restrict__ bgv,
    const float* __restrict__ Wo, const float* __restrict__ bov)
{
    extern __shared__ float smf[];
    float* Asm = smf;
    float* Bsm = smf + 2 * GA_ABUF;
    const uint32_t a_u32 = smem_u32(Asm);
    const uint32_t b_u32 = smem_u32(Bsm);

    const int tid  = threadIdx.x;
    const int w    = tid >> 5;
    const int lane = tid & 31;
    const int r4   = lane >> 2;
    const int j    = lane & 3;
    const int wm0  = (w & 3) * 32;
    const int wn0  = (w >> 2) * 64;

    const int m0 = blockIdx.y * 128;
    const int n0 = blockIdx.x * 128;
    const int gate = n0 >> 10;
    const int u0l  = n0 & 1023;

    const float* W    = (gate == 0) ? Wf  : (gate == 1) ? Wi  : (gate == 2) ? Wg  : Wo;
    const float* bias = (gate == 0) ? bfv : (gate == 1) ? biv : (gate == 2) ? bgv : bov;

    float acc[2][8][4];
#pragma unroll
    for (int mt = 0; mt < 2; mt++)
#pragma unroll
        for (int nt = 0; nt < 8; nt++)
#pragma unroll
            for (int p = 0; p < 4; p++) acc[mt][nt][p] = 0.f;

#define GA_LOAD(BUF, K0) do {                                                  \
    uint32_t ab = a_u32 + (uint32_t)((BUF) * GA_ABUF * 4);                     \
    uint32_t bb = b_u32 + (uint32_t)((BUF) * GA_ABUF * 4);                     \
    _Pragma("unroll")                                                          \
    for (int q = 0; q < 4; q++) {                                              \
        int idx = q * 256 + tid;                                               \
        int row = idx >> 3;                                                    \
        int kq = idx & 7;                                                      \
        uint32_t so = (uint32_t)((row * GA_STR + kq * 4) * 4);                 \
        cp16ca(ab + so, X + (size_t)(m0 + row) * DIM + (K0) + kq * 4);         \
        cp16ca(bb + so, W + (size_t)(u0l + row) * KW + (K0) + kq * 4);         \
    }                                                                          \
    CP_COMMIT(); } while (0)

    GA_LOAD(0, 0);
    int buf = 0;
#pragma unroll 1
    for (int k0 = 0; k0 < DIM; k0 += GA_BK) {
        if (k0 + GA_BK < DIM) { GA_LOAD(buf ^ 1, k0 + GA_BK); CP_WAIT(1); }
        else                  { CP_WAIT(0); }
        __syncthreads();

        const float* Ab = Asm + buf * GA_ABUF;
        const float* Bb = Bsm + buf * GA_ABUF;
#pragma unroll
        for (int kt = 0; kt < 4; kt++) {
            uint32_t a[2][4];
#pragma unroll
            for (int mt = 0; mt < 2; mt++) {
                const float* ap = Ab + (wm0 + mt * 16 + r4) * GA_STR + kt * 8 + j;
                a[mt][0] = f2tf32(ap[0]);
                a[mt][1] = f2tf32(ap[8 * GA_STR]);
                a[mt][2] = f2tf32(ap[4]);
                a[mt][3] = f2tf32(ap[8 * GA_STR + 4]);
            }
#pragma unroll
            for (int nt = 0; nt < 8; nt++) {
                const float* bp = Bb + (wn0 + nt * 8 + r4) * GA_STR + kt * 8 + j;
                uint32_t b0 = f2tf32(bp[0]);
                uint32_t b1 = f2tf32(bp[4]);
                mma_tf32(acc[0][nt], a[0][0], a[0][1], a[0][2], a[0][3], b0, b1);
                mma_tf32(acc[1][nt], a[1][0], a[1][1], a[1][2], a[1][3], b0, b1);
            }
        }
        __syncthreads();
        buf ^= 1;
    }
#undef GA_LOAD

#pragma unroll
    for (int nt = 0; nt < 8; nt++) {
        int gcol = wn0 + nt * 8 + 2 * j;
        float2 bb2 = *(const float2*)(bias + u0l + gcol);
#pragma unroll
        for (int mt = 0; mt < 2; mt++) {
            int gm = m0 + wm0 + mt * 16 + r4;
            float* d0 = g_gx + (size_t)gm * G4 + gate * HID + u0l + gcol;
            *(float2*)d0 = make_float2(acc[mt][nt][0] + bb2.x, acc[mt][nt][1] + bb2.y);
            float* d1 = d0 + 8 * G4;
            *(float2*)d1 = make_float2(acc[mt][nt][2] + bb2.x, acc[mt][nt][3] + bb2.y);
        }
    }
}

// =====================================================================
// Phase B: persistent recurrence, mma.sync tf32, flag-based grid barrier.
// =====================================================================
#define RB_BLOCKS 128
#define RB_THREADS 256

#define STG_BUF  (64 * 36)
#define STG_WARP (2 * STG_BUF)
#define RED_OFF  (8 * STG_WARP)
#define RED_WARP (64 * 34)
#define SMF_TOTAL (RED_OFF + 8 * RED_WARP)

__global__ __launch_bounds__(RB_THREADS, 1) void lstm_rec_kernel(
    const float* __restrict__ Wf, const float* __restrict__ Wi,
    const float* __restrict__ Wg, const float* __restrict__ Wo,
    float* __restrict__ out, long long out_size)
{
    extern __shared__ float smf[];
    const int tid  = threadIdx.x;
    const int g    = tid >> 5;
    const int lane = tid & 31;
    const int r4   = lane >> 2;
    const int j    = lane & 3;
    const int u0   = blockIdx.x * 8;

    const uint32_t stg_u32 = smem_u32(smf);

    // ---- register-resident weight fragments (tf32) ----
    uint32_t bfr[16][4][2];
#pragma unroll
    for (int nt = 0; nt < 4; nt++) {
        int col = nt * 8 + r4;
        int gate = col & 3;
        int ui = col >> 2;
        const float* Wq = (gate == 0) ? Wf : (gate == 1) ? Wi : (gate == 2) ? Wg : Wo;
        const float* wrow = Wq + (size_t)(u0 + ui) * KW + DIM + g * 128 + j;
#pragma unroll
        for (int kt = 0; kt < 16; kt++) {
            bfr[kt][nt][0] = f2tf32(__ldg(wrow + kt * 8));
            bfr[kt][nt][1] = f2tf32(__ldg(wrow + kt * 8 + 4));
        }
    }

    const int erow = tid >> 2;
    const int eup  = tid & 3;

    float c_reg0 = 0.f, c_reg1 = 0.f;

#define ISSUE_CHUNK(CC) do {                                                   \
    uint32_t dbase = stg_u32 + (uint32_t)((g * STG_WARP + ((CC) & 1) * STG_BUF) * 4); \
    const float* hs_ = hsrc + g * 128 + (CC) * 32;                             \
    _Pragma("unroll")                                                          \
    for (int q = 0; q < 16; q++) {                                             \
        int idx = q * 32 + lane;                                               \
        int row = idx >> 3;                                                    \
        int k4 = idx & 7;                                                      \
        cp16(dbase + (uint32_t)((row * 36 + k4 * 4) * 4),                      \
             hs_ + (size_t)row * HID + k4 * 4);                                \
    }                                                                          \
    CP_COMMIT(); } while (0)

#define CONSUME_CHUNK(CC) do {                                                 \
    const float* sbuf_ = smf + g * STG_WARP + ((CC) & 1) * STG_BUF;            \
    _Pragma("unroll")                                                          \
    for (int kt = 0; kt < 4; kt++) {                                           \
        _Pragma("unroll")                                                      \
        for (int rt = 0; rt < 4; rt++) {                                       \
            const float* ap = sbuf_ + (rt * 16 + r4) * 36 + kt * 8 + j;        \
            uint32_t a0 = f2tf32(ap[0]);                                       \
            uint32_t a2 = f2tf32(ap[4]);                                       \
            uint32_t a1 = f2tf32(ap[8 * 36]);                                  \
            uint32_t a3 = f2tf32(ap[8 * 36 + 4]);                              \
            _Pragma("unroll")                                                  \
            for (int nt = 0; nt < 4; nt++) {                                   \
                mma_tf32(acc[rt][nt], a0, a1, a2, a3,                          \
                         bfr[(CC) * 4 + kt][nt][0], bfr[(CC) * 4 + kt][nt][1]); \
            }                                                                  \
        }                                                                      \
    } } while (0)

    // gx prefetch for t=0
    float gxv[8];
    {
        const float* gxr = g_gx + (size_t)erow * G4 + u0 + eup * 2;
#pragma unroll
        for (int gate = 0; gate < 4; gate++) {
            float2 v = __ldcg((const float2*)(gxr + gate * HID));
            gxv[gate] = v.x;
            gxv[4 + gate] = v.y;
        }
    }

    int* const my_flag = g_flags + blockIdx.x * 32;

    for (int t = 0; t < T_STEPS; ++t) {
        if (t > 0) {
            const float* hsrc = g_h + (size_t)((t - 1) & 1) * (BATCH * HID);
            float acc[4][4][4];
#pragma unroll
            for (int rt = 0; rt < 4; rt++)
#pragma unroll
                for (int nt = 0; nt < 4; nt++)
#pragma unroll
                    for (int p = 0; p < 4; p++) acc[rt][nt][p] = 0.f;

            ISSUE_CHUNK(0);
            ISSUE_CHUNK(1);
            CP_WAIT(1); __syncwarp();
            CONSUME_CHUNK(0);
            ISSUE_CHUNK(2);
            CP_WAIT(1); __syncwarp();
            CONSUME_CHUNK(1);
            ISSUE_CHUNK(3);
            CP_WAIT(1); __syncwarp();
            CONSUME_CHUNK(2);
            CP_WAIT(0); __syncwarp();
            CONSUME_CHUNK(3);

            float* rw = smf + RED_OFF + g * RED_WARP;
#pragma unroll
            for (int rt = 0; rt < 4; rt++)
#pragma unroll
                for (int nt = 0; nt < 4; nt++) {
                    int r0 = rt * 16 + r4;
                    int c0 = nt * 8 + j * 2;
                    *(float2*)(rw + r0 * 34 + c0)       = make_float2(acc[rt][nt][0], acc[rt][nt][1]);
                    *(float2*)(rw + (r0 + 8) * 34 + c0) = make_float2(acc[rt][nt][2], acc[rt][nt][3]);
                }
        }
        __syncthreads();

        // ---- reduction + activations (pre[gate]=unit0, pre[4+gate]=unit1) ----
        float pre[8];
#pragma unroll
        for (int loc = 0; loc < 8; loc++) {
            float s = gxv[loc];
            if (t > 0) {
                const float* rp = smf + RED_OFF + erow * 34 + eup * 8 + loc;
#pragma unroll
                for (int gg = 0; gg < 8; gg++) s += rp[gg * RED_WARP];
            }
            pre[loc] = s;
        }

        float h0, h1;
        {
            float fg = 1.f / (1.f + __expf(-pre[0]));
            float ig = 1.f / (1.f + __expf(-pre[1]));
            float gv = 2.f / (1.f + __expf(-2.f * pre[2])) - 1.f;
            float og = 1.f / (1.f + __expf(-pre[3]));
            float cn = fg * c_reg0 + ig * gv;
            c_reg0 = cn;
            h0 = og * (2.f / (1.f + __expf(-2.f * cn)) - 1.f);

            fg = 1.f / (1.f + __expf(-pre[4]));
            ig = 1.f / (1.f + __expf(-pre[5]));
            gv = 2.f / (1.f + __expf(-2.f * pre[6])) - 1.f;
            og = 1.f / (1.f + __expf(-pre[7]));
            cn = fg * c_reg1 + ig * gv;
            c_reg1 = cn;
            h1 = og * (2.f / (1.f + __expf(-2.f * cn)) - 1.f);
        }

        size_t hoff = (size_t)erow * HID + u0 + eup * 2;
        float* hdst = g_h + (size_t)(t & 1) * (BATCH * HID);
        *(float2*)(hdst + hoff) = make_float2(h0, h1);

        if (t < T_STEPS - 1) {
            // ---- flag barrier: publish h, then signal own flag ----
            __threadfence();
            __syncthreads();
            if (tid == 0) {
                __threadfence();
                asm volatile("st.global.cg.u32 [%0], %1;" :: "l"(my_flag), "r"(t + 1) : "memory");
            }
            // overlap: out store + gx(t+1) prefetch during barrier window
            *(float2*)(out + (size_t)t * (BATCH * HID) + hoff) = make_float2(h0, h1);
            {
                const float* gxr = g_gx + (size_t)(t + 1) * BATCH * G4 + (size_t)erow * G4 + u0 + eup * 2;
#pragma unroll
                for (int gate = 0; gate < 4; gate++) {
                    float2 v = __ldcg((const float2*)(gxr + gate * HID));
                    gxv[gate] = v.x;
                    gxv[4 + gate] = v.y;
                }
            }
            // ---- poll: thread b waits on block b's flag ----
            if (tid < RB_BLOCKS) {
                const int* fp = g_flags + tid * 32;
                int v;
                while (true) {
                    asm volatile("ld.global.cg.u32 %0, [%1];" : "=r"(v) : "l"(fp) : "memory");
                    if (v >= t + 1) break;
                    __nanosleep(16);
                }
                __threadfence();   // acquire: order h reads after flag observation
            }
            __syncthreads();
        } else {
            *(float2*)(out + (size_t)t * (BATCH * HID) + hoff) = make_float2(h0, h1);
            long long base = (long long)T_STEPS * BATCH * HID;
            long long ho = base + (long long)hoff;
            long long co = base + (long long)(BATCH * HID) + (long long)hoff;
            if (ho + 1 < out_size) { out[ho] = h0; out[ho + 1] = h1; }
            if (co + 1 < out_size) { out[co] = c_reg0; out[co + 1] = c_reg1; }
        }
    }
#undef ISSUE_CHUNK
#undef CONSUME_CHUNK

    // ---- replay-safe cleanup: everyone past all polls, then reset flags ----
    grid_bar_atomic(RB_BLOCKS);
    if (tid == 0) {
        asm volatile("st.global.cg.u32 [%0], %1;" :: "l"(my_flag), "r"(0) : "memory");
    }
}

// =====================================================================
extern "C" void kernel_launch(void* const* d_in, const int* in_sizes, int n_in,
                              void* d_out, int out_size)
{
    const float* inputs = (const float*)d_in[0];
    const float* Wf = (const float*)d_in[1];
    const float* bf = (const float*)d_in[2];
    const float* Wi = (const float*)d_in[3];
    const float* bi = (const float*)d_in[4];
    const float* Wg = (const float*)d_in[5];
    const float* bg = (const float*)d_in[6];
    const float* Wo = (const float*)d_in[7];
    const float* bo = (const float*)d_in[8];
    float* out = (float*)d_out;

    cudaFuncSetAttribute(gemm_x_tc, cudaFuncAttributeMaxDynamicSharedMemorySize, GA_SMEM);
    dim3 gridA(G4 / 128, (T_STEPS * BATCH) / 128);
    gemm_x_tc<<<gridA, 256, GA_SMEM>>>(inputs, Wf, bf, Wi, bi, Wg, bg, Wo, bo);

    int smem_bytes = SMF_TOTAL * (int)sizeof(float);
    cudaFuncSetAttribute(lstm_rec_kernel, cudaFuncAttributeMaxDynamicSharedMemorySize, smem_bytes);
    lstm_rec_kernel<<<RB_BLOCKS, RB_THREADS, smem_bytes>>>(Wf, Wi, Wg, Wo, out, (long long)out_size);
}